// round 2
// baseline (speedup 1.0000x reference)
#include <cuda_runtime.h>

#define N_NODES 100000
#define N_EDGES 1600000
#define D_IN    128
#define D_OUT   64

// Scratch: h = x @ W   (100000 x 64 fp32 = 25.6 MB, L2-resident)
__device__ __align__(256) float g_h[N_NODES * D_OUT];

// Index-width flag: 1 = indices are int64, 0 = int32
__device__ int g_idx64;

// ---------------------------------------------------------------------------
// Probe: decide at runtime whether index tensors are int64 or int32.
// int32 data read as u64 packs two indices -> top 32 bits nonzero w.h.p.
// ---------------------------------------------------------------------------
__global__ void probe_kernel(const void* __restrict__ src) {
    const unsigned long long* p = (const unsigned long long*)src;
    int is64 = 1;
    for (int i = 0; i < 8; i++)
        if (p[i] >= (unsigned long long)N_NODES) is64 = 0;
    g_idx64 = is64;
}

// ---------------------------------------------------------------------------
// Kernel 1: h = x @ W.  Block: 256 threads, tile 32 rows x 64 cols.
// Thread tile: 2 rows x 4 cols. W (32KB) + X tile (16KB) in shared = 48KB.
// ---------------------------------------------------------------------------
__global__ void __launch_bounds__(256) gemm_kernel(const float* __restrict__ x,
                                                   const float* __restrict__ W) {
    __shared__ float Ws[D_IN * D_OUT];   // 32 KB
    __shared__ float Xs[32 * D_IN];      // 16 KB

    const int tid = threadIdx.x;

    const float4* Wg  = (const float4*)W;
    float4*       Wsv = (float4*)Ws;
#pragma unroll
    for (int i = 0; i < 8; i++) Wsv[tid + i * 256] = Wg[tid + i * 256];

    const int row0 = blockIdx.x * 32;
    const float4* Xg  = (const float4*)(x + (size_t)row0 * D_IN);
    float4*       Xsv = (float4*)Xs;
#pragma unroll
    for (int i = 0; i < 4; i++) Xsv[tid + i * 256] = Xg[tid + i * 256];

    __syncthreads();

    const int tx = tid & 15;   // column group: cols [4*tx, 4*tx+3]
    const int ty = tid >> 4;   // row group: rows 2*ty, 2*ty+1

    float4 acc0 = {0.f, 0.f, 0.f, 0.f};
    float4 acc1 = {0.f, 0.f, 0.f, 0.f};

#pragma unroll
    for (int k0 = 0; k0 < D_IN; k0 += 4) {
        const float4 xa = *(const float4*)&Xs[(2 * ty)     * D_IN + k0];
        const float4 xb = *(const float4*)&Xs[(2 * ty + 1) * D_IN + k0];
        const float xav[4] = {xa.x, xa.y, xa.z, xa.w};
        const float xbv[4] = {xb.x, xb.y, xb.z, xb.w};
#pragma unroll
        for (int j = 0; j < 4; j++) {
            const float4 wv = *(const float4*)&Ws[(k0 + j) * D_OUT + 4 * tx];
            acc0.x += xav[j] * wv.x;  acc0.y += xav[j] * wv.y;
            acc0.z += xav[j] * wv.z;  acc0.w += xav[j] * wv.w;
            acc1.x += xbv[j] * wv.x;  acc1.y += xbv[j] * wv.y;
            acc1.z += xbv[j] * wv.z;  acc1.w += xbv[j] * wv.w;
        }
    }

    float4* h0 = (float4*)&g_h[(size_t)(row0 + 2 * ty)     * D_OUT + 4 * tx];
    float4* h1 = (float4*)&g_h[(size_t)(row0 + 2 * ty + 1) * D_OUT + 4 * tx];
    *h0 = acc0;
    *h1 = acc1;
}

// ---------------------------------------------------------------------------
// Kernel 2: zero the output (it arrives poisoned)
// ---------------------------------------------------------------------------
__global__ void __launch_bounds__(256) zero_kernel(float4* __restrict__ out) {
    out[blockIdx.x * 256 + threadIdx.x] = make_float4(0.f, 0.f, 0.f, 0.f);
}

// ---------------------------------------------------------------------------
// Kernel 3: scatter.  out[src] += w * h[dst].  16 threads per edge, each
// handles one float4 (16B) of the 256B row.  red.global.add.v4.f32 cuts
// atomic lane count 4x vs scalar atomics.
// ---------------------------------------------------------------------------
__global__ void __launch_bounds__(256) scatter_kernel(
    const float* __restrict__ ew,
    const void* __restrict__ srcp,
    const void* __restrict__ dstp,
    float* __restrict__ out) {

    const int t = blockIdx.x * 256 + threadIdx.x;   // 25.6M threads, exact
    const int e = t >> 4;
    const int c = t & 15;
    const int lane = threadIdx.x & 31;
    const int bsrc = lane & 16;                      // broadcast source lane

    const int idx64 = g_idx64;                       // uniform load

    long long s = 0, d = 0;
    float w = 0.f;
    if ((lane & 15) == 0) {
        if (idx64) {
            s = ((const long long*)srcp)[e];
            d = ((const long long*)dstp)[e];
        } else {
            s = ((const int*)srcp)[e];
            d = ((const int*)dstp)[e];
        }
        w = ew[e];
    }
    s = __shfl_sync(0xffffffffu, s, bsrc);
    d = __shfl_sync(0xffffffffu, d, bsrc);
    w = __shfl_sync(0xffffffffu, w, bsrc);

    // Defensive: wrong answers beat crashes if dtype assumptions are off.
    if ((unsigned long long)s >= N_NODES || (unsigned long long)d >= N_NODES)
        return;

    const float4 v = __ldg((const float4*)(g_h + (size_t)d * D_OUT) + c);

    float* p = out + (size_t)s * D_OUT + 4 * c;
    asm volatile("red.global.add.v4.f32 [%0], {%1, %2, %3, %4};"
                 :: "l"(p), "f"(v.x * w), "f"(v.y * w), "f"(v.z * w), "f"(v.w * w)
                 : "memory");
}

// ---------------------------------------------------------------------------
// Kernel 4: in-place ReLU
// ---------------------------------------------------------------------------
__global__ void __launch_bounds__(256) relu_kernel(float4* __restrict__ out) {
    const int i = blockIdx.x * 256 + threadIdx.x;
    float4 v = out[i];
    v.x = fmaxf(v.x, 0.f);
    v.y = fmaxf(v.y, 0.f);
    v.z = fmaxf(v.z, 0.f);
    v.w = fmaxf(v.w, 0.f);
    out[i] = v;
}

// ---------------------------------------------------------------------------
extern "C" void kernel_launch(void* const* d_in, const int* in_sizes, int n_in,
                              void* d_out, int out_size) {
    const float* x   = (const float*)d_in[0];      // [100000, 128]
    const float* ew  = (const float*)d_in[1];      // [1600000]
    const float* W   = (const float*)d_in[2];      // [128, 64]
    const void*  src = d_in[3];                    // [1600000] int64 or int32
    const void*  dst = d_in[4];                    // [1600000] int64 or int32
    float* out = (float*)d_out;                    // [100000, 64]

    probe_kernel<<<1, 1>>>(src);

    // out: 6.4M floats = 1.6M float4 -> 6250 blocks
    zero_kernel<<<(N_NODES * D_OUT) / 4 / 256, 256>>>((float4*)out);

    // h = x @ W : 100000 rows / 32 per block = 3125 blocks
    gemm_kernel<<<N_NODES / 32, 256>>>(x, W);

    // scatter: E*16 threads = 25.6M -> 100000 blocks
    scatter_kernel<<<(N_EDGES * 16) / 256, 256>>>(ew, src, dst, out);

    // ReLU over 1.6M float4
    relu_kernel<<<(N_NODES * D_OUT) / 4 / 256, 256>>>((float4*)out);
}

// round 3
// speedup vs baseline: 1.1716x; 1.1716x over previous
#include <cuda_runtime.h>

#define N_NODES 100000
#define N_EDGES 1600000
#define D_IN    128
#define D_OUT   64

// Scratch: h = x @ W   (100000 x 64 fp32 = 25.6 MB, L2-resident)
__device__ __align__(256) float g_h[N_NODES * D_OUT];

// Index-width flag: 1 = indices are int64, 0 = int32
__device__ int g_idx64;

// ---------------------------------------------------------------------------
// Kernel 1: zero output (poisoned by harness) + index-width probe (block 0).
// int32 data read as u64 packs two indices -> top 32 bits nonzero w.h.p.
// ---------------------------------------------------------------------------
__global__ void __launch_bounds__(256) zero_probe_kernel(
    float4* __restrict__ out, const void* __restrict__ src) {
    if (blockIdx.x == 0 && threadIdx.x == 0) {
        const unsigned long long* p = (const unsigned long long*)src;
        int is64 = 1;
        for (int i = 0; i < 8; i++)
            if (p[i] >= (unsigned long long)N_NODES) is64 = 0;
        g_idx64 = is64;
    }
    out[blockIdx.x * 256 + threadIdx.x] = make_float4(0.f, 0.f, 0.f, 0.f);
}

// ---------------------------------------------------------------------------
// Kernel 2: h = x @ W.  256 threads, tile 32 rows x 64 cols, thread tile
// 2 rows x 4 cols.  Inner product uses packed fma.rn.f32x2 (2x FFMA rate).
// ---------------------------------------------------------------------------
__global__ void __launch_bounds__(256) gemm_kernel(const float* __restrict__ x,
                                                   const float* __restrict__ W) {
    __shared__ float Ws[D_IN * D_OUT];   // 32 KB
    __shared__ float Xs[32 * D_IN];      // 16 KB

    const int tid = threadIdx.x;

    const float4* Wg  = (const float4*)W;
    float4*       Wsv = (float4*)Ws;
#pragma unroll
    for (int i = 0; i < 8; i++) Wsv[tid + i * 256] = Wg[tid + i * 256];

    const int row0 = blockIdx.x * 32;
    const float4* Xg  = (const float4*)(x + (size_t)row0 * D_IN);
    float4*       Xsv = (float4*)Xs;
#pragma unroll
    for (int i = 0; i < 4; i++) Xsv[tid + i * 256] = Xg[tid + i * 256];

    __syncthreads();

    const int tx = tid & 15;   // cols [4*tx, 4*tx+3]
    const int ty = tid >> 4;   // rows 2*ty, 2*ty+1

    unsigned long long a00 = 0ull, a01 = 0ull, a10 = 0ull, a11 = 0ull;

#pragma unroll
    for (int k0 = 0; k0 < D_IN; k0 += 4) {
        const float4 xa = *(const float4*)&Xs[(2 * ty)     * D_IN + k0];
        const float4 xb = *(const float4*)&Xs[(2 * ty + 1) * D_IN + k0];
        const float xav[4] = {xa.x, xa.y, xa.z, xa.w};
        const float xbv[4] = {xb.x, xb.y, xb.z, xb.w};
#pragma unroll
        for (int j = 0; j < 4; j++) {
            const ulonglong2 wv =
                *(const ulonglong2*)&Ws[(k0 + j) * D_OUT + 4 * tx];
            unsigned long long da, db;
            asm("mov.b64 %0, {%1, %1};" : "=l"(da) : "f"(xav[j]));
            asm("mov.b64 %0, {%1, %1};" : "=l"(db) : "f"(xbv[j]));
            asm("fma.rn.f32x2 %0, %1, %2, %0;" : "+l"(a00) : "l"(da), "l"(wv.x));
            asm("fma.rn.f32x2 %0, %1, %2, %0;" : "+l"(a01) : "l"(da), "l"(wv.y));
            asm("fma.rn.f32x2 %0, %1, %2, %0;" : "+l"(a10) : "l"(db), "l"(wv.x));
            asm("fma.rn.f32x2 %0, %1, %2, %0;" : "+l"(a11) : "l"(db), "l"(wv.y));
        }
    }

    float4 r0, r1;
    asm("mov.b64 {%0, %1}, %2;" : "=f"(r0.x), "=f"(r0.y) : "l"(a00));
    asm("mov.b64 {%0, %1}, %2;" : "=f"(r0.z), "=f"(r0.w) : "l"(a01));
    asm("mov.b64 {%0, %1}, %2;" : "=f"(r1.x), "=f"(r1.y) : "l"(a10));
    asm("mov.b64 {%0, %1}, %2;" : "=f"(r1.z), "=f"(r1.w) : "l"(a11));

    *(float4*)&g_h[(size_t)(row0 + 2 * ty)     * D_OUT + 4 * tx] = r0;
    *(float4*)&g_h[(size_t)(row0 + 2 * ty + 1) * D_OUT + 4 * tx] = r1;
}

// ---------------------------------------------------------------------------
// Kernel 3: scatter.  out[src] += w * h[dst].  16 lanes per edge (one float4
// each), 2 edges per thread for MLP.  Indices loaded directly by every lane
// (same cacheline -> L1 broadcast, no shfl chain); int64 indices read via
// their low 32-bit word only.
// ---------------------------------------------------------------------------
__global__ void __launch_bounds__(256) scatter_kernel(
    const float* __restrict__ ew,
    const void* __restrict__ srcp,
    const void* __restrict__ dstp,
    float* __restrict__ out) {

    const int t  = blockIdx.x * 256 + threadIdx.x;   // 12.8M threads, exact
    const int c  = t & 15;                           // float4 slot in row
    const int g  = t >> 4;                           // edge-pair group
    const int e0 = 2 * g;
    const int e1 = e0 + 1;

    const int idx64 = g_idx64;

    const int* sp = (const int*)srcp;
    const int* dp = (const int*)dstp;

    int s0, d0, s1, d1;
    if (idx64) {   // little-endian low words of int64
        s0 = __ldg(sp + 2 * e0);  d0 = __ldg(dp + 2 * e0);
        s1 = __ldg(sp + 2 * e1);  d1 = __ldg(dp + 2 * e1);
    } else {
        s0 = __ldg(sp + e0);      d0 = __ldg(dp + e0);
        s1 = __ldg(sp + e1);      d1 = __ldg(dp + e1);
    }
    const float w0 = __ldg(ew + e0);
    const float w1 = __ldg(ew + e1);

    const float4 v0 = __ldg((const float4*)(g_h + (size_t)d0 * D_OUT) + c);
    const float4 v1 = __ldg((const float4*)(g_h + (size_t)d1 * D_OUT) + c);

    if ((unsigned)s0 < N_NODES) {
        float* p = out + (size_t)s0 * D_OUT + 4 * c;
        asm volatile("red.global.add.v4.f32 [%0], {%1, %2, %3, %4};"
                     :: "l"(p), "f"(v0.x * w0), "f"(v0.y * w0),
                        "f"(v0.z * w0), "f"(v0.w * w0) : "memory");
    }
    if ((unsigned)s1 < N_NODES) {
        float* p = out + (size_t)s1 * D_OUT + 4 * c;
        asm volatile("red.global.add.v4.f32 [%0], {%1, %2, %3, %4};"
                     :: "l"(p), "f"(v1.x * w1), "f"(v1.y * w1),
                        "f"(v1.z * w1), "f"(v1.w * w1) : "memory");
    }
}

// ---------------------------------------------------------------------------
// Kernel 4: in-place ReLU
// ---------------------------------------------------------------------------
__global__ void __launch_bounds__(256) relu_kernel(float4* __restrict__ out) {
    const int i = blockIdx.x * 256 + threadIdx.x;
    float4 v = out[i];
    v.x = fmaxf(v.x, 0.f);
    v.y = fmaxf(v.y, 0.f);
    v.z = fmaxf(v.z, 0.f);
    v.w = fmaxf(v.w, 0.f);
    out[i] = v;
}

// ---------------------------------------------------------------------------
extern "C" void kernel_launch(void* const* d_in, const int* in_sizes, int n_in,
                              void* d_out, int out_size) {
    const float* x   = (const float*)d_in[0];      // [100000, 128]
    const float* ew  = (const float*)d_in[1];      // [1600000]
    const float* W   = (const float*)d_in[2];      // [128, 64]
    const void*  src = d_in[3];                    // [1600000] int64/int32
    const void*  dst = d_in[4];                    // [1600000] int64/int32
    float* out = (float*)d_out;                    // [100000, 64]

    // zero 1.6M float4 (+ probe in block 0)
    zero_probe_kernel<<<(N_NODES * D_OUT) / 4 / 256, 256>>>((float4*)out, src);

    // h = x @ W : 3125 blocks
    gemm_kernel<<<N_NODES / 32, 256>>>(x, W);

    // scatter: E*16/2 threads = 12.8M -> 50000 blocks
    scatter_kernel<<<(N_EDGES * 8) / 256, 256>>>(ew, src, dst, out);

    // ReLU over 1.6M float4
    relu_kernel<<<(N_NODES * D_OUT) / 4 / 256, 256>>>((float4*)out);
}

// round 4
// speedup vs baseline: 1.2411x; 1.0593x over previous
#include <cuda_runtime.h>

#define N_NODES 100000
#define N_EDGES 1600000
#define D_IN    128
#define D_OUT   64

// Scratch: h = x @ W   (100000 x 64 fp32 = 25.6 MB, L2-resident)
__device__ __align__(256) float g_h[N_NODES * D_OUT];

// Index-width flag: 1 = indices are int64, 0 = int32
__device__ int g_idx64;

// ---------------------------------------------------------------------------
// Kernel 1: h = x @ W  (+ index-width probe in block 0).
// 256 threads, tile 32 rows x 64 cols, thread tile 2 rows x 4 cols.
// Inner product uses packed fma.rn.f32x2 (2x FFMA rate).
// ---------------------------------------------------------------------------
__global__ void __launch_bounds__(256) gemm_kernel(const float* __restrict__ x,
                                                   const float* __restrict__ W,
                                                   const void* __restrict__ src) {
    __shared__ float Ws[D_IN * D_OUT];   // 32 KB
    __shared__ float Xs[32 * D_IN];      // 16 KB

    const int tid = threadIdx.x;

    if (blockIdx.x == 0 && tid == 0) {
        // int32 data read as u64 packs two indices -> top bits nonzero w.h.p.
        const unsigned long long* p = (const unsigned long long*)src;
        int is64 = 1;
        for (int i = 0; i < 8; i++)
            if (p[i] >= (unsigned long long)N_NODES) is64 = 0;
        g_idx64 = is64;
    }

    const float4* Wg  = (const float4*)W;
    float4*       Wsv = (float4*)Ws;
#pragma unroll
    for (int i = 0; i < 8; i++) Wsv[tid + i * 256] = Wg[tid + i * 256];

    const int row0 = blockIdx.x * 32;
    const float4* Xg  = (const float4*)(x + (size_t)row0 * D_IN);
    float4*       Xsv = (float4*)Xs;
#pragma unroll
    for (int i = 0; i < 4; i++) Xsv[tid + i * 256] = Xg[tid + i * 256];

    __syncthreads();

    const int tx = tid & 15;   // cols [4*tx, 4*tx+3]
    const int ty = tid >> 4;   // rows 2*ty, 2*ty+1

    unsigned long long a00 = 0ull, a01 = 0ull, a10 = 0ull, a11 = 0ull;

#pragma unroll
    for (int k0 = 0; k0 < D_IN; k0 += 4) {
        const float4 xa = *(const float4*)&Xs[(2 * ty)     * D_IN + k0];
        const float4 xb = *(const float4*)&Xs[(2 * ty + 1) * D_IN + k0];
        const float xav[4] = {xa.x, xa.y, xa.z, xa.w};
        const float xbv[4] = {xb.x, xb.y, xb.z, xb.w};
#pragma unroll
        for (int j = 0; j < 4; j++) {
            const ulonglong2 wv =
                *(const ulonglong2*)&Ws[(k0 + j) * D_OUT + 4 * tx];
            unsigned long long da, db;
            asm("mov.b64 %0, {%1, %1};" : "=l"(da) : "f"(xav[j]));
            asm("mov.b64 %0, {%1, %1};" : "=l"(db) : "f"(xbv[j]));
            asm("fma.rn.f32x2 %0, %1, %2, %0;" : "+l"(a00) : "l"(da), "l"(wv.x));
            asm("fma.rn.f32x2 %0, %1, %2, %0;" : "+l"(a01) : "l"(da), "l"(wv.y));
            asm("fma.rn.f32x2 %0, %1, %2, %0;" : "+l"(a10) : "l"(db), "l"(wv.x));
            asm("fma.rn.f32x2 %0, %1, %2, %0;" : "+l"(a11) : "l"(db), "l"(wv.y));
        }
    }

    float4 r0, r1;
    asm("mov.b64 {%0, %1}, %2;" : "=f"(r0.x), "=f"(r0.y) : "l"(a00));
    asm("mov.b64 {%0, %1}, %2;" : "=f"(r0.z), "=f"(r0.w) : "l"(a01));
    asm("mov.b64 {%0, %1}, %2;" : "=f"(r1.x), "=f"(r1.y) : "l"(a10));
    asm("mov.b64 {%0, %1}, %2;" : "=f"(r1.z), "=f"(r1.w) : "l"(a11));

    *(float4*)&g_h[(size_t)(row0 + 2 * ty)     * D_OUT + 4 * tx] = r0;
    *(float4*)&g_h[(size_t)(row0 + 2 * ty + 1) * D_OUT + 4 * tx] = r1;
}

// ---------------------------------------------------------------------------
// Kernel 2: scatter.  out[src] += w * h[dst].  16 lanes per edge (one float4
// each), 4 edges per thread: all index loads batched first, then 4
// independent gather->red chains in flight (MLP).
// ---------------------------------------------------------------------------
__global__ void __launch_bounds__(256) scatter_kernel(
    const float* __restrict__ ew,
    const void* __restrict__ srcp,
    const void* __restrict__ dstp,
    float* __restrict__ out) {

    const int t  = blockIdx.x * 256 + threadIdx.x;   // 6.4M threads, exact
    const int c  = t & 15;                           // float4 slot in row
    const int g  = t >> 4;                           // edge quad
    const int e0 = 4 * g;

    const int idx64 = g_idx64;

    const int* sp = (const int*)srcp;
    const int* dp = (const int*)dstp;

    int s[4], d[4];
    float w[4];
#pragma unroll
    for (int i = 0; i < 4; i++) {
        const int e = e0 + i;
        if (idx64) {                 // little-endian low words of int64
            s[i] = __ldg(sp + 2 * e);
            d[i] = __ldg(dp + 2 * e);
        } else {
            s[i] = __ldg(sp + e);
            d[i] = __ldg(dp + e);
        }
        w[i] = __ldg(ew + e);
    }

    float4 v[4];
#pragma unroll
    for (int i = 0; i < 4; i++)
        v[i] = __ldg((const float4*)(g_h + (size_t)d[i] * D_OUT) + c);

#pragma unroll
    for (int i = 0; i < 4; i++) {
        if ((unsigned)s[i] < N_NODES) {
            float* p = out + (size_t)s[i] * D_OUT + 4 * c;
            asm volatile("red.global.add.v4.f32 [%0], {%1, %2, %3, %4};"
                         :: "l"(p), "f"(v[i].x * w[i]), "f"(v[i].y * w[i]),
                            "f"(v[i].z * w[i]), "f"(v[i].w * w[i]) : "memory");
        }
    }
}

// ---------------------------------------------------------------------------
// Kernel 3: in-place ReLU, 2 float4 per thread
// ---------------------------------------------------------------------------
#define RELU_HALF (N_NODES * D_OUT / 4 / 2)   // 800000 float4 per half

__global__ void __launch_bounds__(256) relu_kernel(float4* __restrict__ out) {
    const int i = blockIdx.x * 256 + threadIdx.x;
    float4 a = out[i];
    float4 b = out[i + RELU_HALF];
    a.x = fmaxf(a.x, 0.f); a.y = fmaxf(a.y, 0.f);
    a.z = fmaxf(a.z, 0.f); a.w = fmaxf(a.w, 0.f);
    b.x = fmaxf(b.x, 0.f); b.y = fmaxf(b.y, 0.f);
    b.z = fmaxf(b.z, 0.f); b.w = fmaxf(b.w, 0.f);
    out[i] = a;
    out[i + RELU_HALF] = b;
}

// ---------------------------------------------------------------------------
extern "C" void kernel_launch(void* const* d_in, const int* in_sizes, int n_in,
                              void* d_out, int out_size) {
    const float* x   = (const float*)d_in[0];      // [100000, 128]
    const float* ew  = (const float*)d_in[1];      // [1600000]
    const float* W   = (const float*)d_in[2];      // [128, 64]
    const void*  src = d_in[3];                    // [1600000] int64/int32
    const void*  dst = d_in[4];                    // [1600000] int64/int32
    float* out = (float*)d_out;                    // [100000, 64]

    // zero the poisoned output (graph-capturable, no alloc)
    cudaMemsetAsync(out, 0, (size_t)N_NODES * D_OUT * sizeof(float));

    // h = x @ W (+probe): 3125 blocks
    gemm_kernel<<<N_NODES / 32, 256>>>(x, W, src);

    // scatter: E*16/4 threads = 6.4M -> 25000 blocks
    scatter_kernel<<<(N_EDGES * 4) / 256, 256>>>(ew, src, dst, out);

    // ReLU: 800000 threads -> 3125 blocks
    relu_kernel<<<RELU_HALF / 256, 256>>>((float4*)out);
}

// round 5
// speedup vs baseline: 1.3200x; 1.0635x over previous
#include <cuda_runtime.h>

#define N_NODES 100000
#define N_EDGES 1600000
#define D_IN    128
#define D_OUT   64

// Scratch: h = x @ W   (100000 x 64 fp32 = 25.6 MB, L2-resident)
__device__ __align__(256) float g_h[N_NODES * D_OUT];

// Index-width flag: 1 = indices are int64, 0 = int32
__device__ int g_idx64;

// ---------------------------------------------------------------------------
// Kernel 1: h = x @ W  (+ index-width probe in block 0).
// 128 threads, block tile 128 rows x 64 cols, thread tile 8 rows x 8 cols.
// K chunked by 32 through smem.  1.0 B smem per MAC -> crossbar and FFMA2
// pipe both ~saturated.
// ---------------------------------------------------------------------------
__global__ void __launch_bounds__(128) gemm_kernel(const float* __restrict__ x,
                                                   const float* __restrict__ W,
                                                   const void* __restrict__ src) {
    __shared__ float Ws[D_IN * D_OUT];   // 32 KB, [k][col]
    __shared__ float Xs[128 * 32];       // 16 KB, [row][k-local]

    const int tid = threadIdx.x;

    if (blockIdx.x == 0 && tid == 0) {
        // int32 data read as u64 packs two indices -> top bits nonzero w.h.p.
        const unsigned long long* p = (const unsigned long long*)src;
        int is64 = 1;
        for (int i = 0; i < 8; i++)
            if (p[i] >= (unsigned long long)N_NODES) is64 = 0;
        g_idx64 = is64;
    }

    // Load all of W: 2048 float4, 16 per thread
    {
        const float4* Wg  = (const float4*)W;
        float4*       Wsv = (float4*)Ws;
#pragma unroll
        for (int i = 0; i < 16; i++) Wsv[tid + i * 128] = Wg[tid + i * 128];
    }

    const int row0 = blockIdx.x * 128;
    const int tx = tid & 7;    // cols [8*tx, 8*tx+7]
    const int ty = tid >> 3;   // rows [8*ty, 8*ty+7] (local)

    unsigned long long acc[8][4];
#pragma unroll
    for (int r = 0; r < 8; r++)
#pragma unroll
        for (int c = 0; c < 4; c++) acc[r][c] = 0ull;

    for (int k0 = 0; k0 < D_IN; k0 += 32) {
        __syncthreads();   // protect Xs from previous chunk's readers
        // Load X chunk [128 rows x 32 k]: 1024 float4, 8 per thread, coalesced
#pragma unroll
        for (int i = 0; i < 8; i++) {
            const int lin  = tid + i * 128;
            const int row  = lin >> 3;
            const int slot = lin & 7;
            int grow = row0 + row;
            if (grow >= N_NODES) grow = N_NODES - 1;   // clamp (dup, unused)
            const float4 v =
                __ldg((const float4*)(x + (size_t)grow * D_IN + k0) + slot);
            *(float4*)&Xs[row * 32 + slot * 4] = v;
        }
        __syncthreads();

#pragma unroll
        for (int kk = 0; kk < 32; kk += 4) {
            float4 xv[8];
#pragma unroll
            for (int r = 0; r < 8; r++)
                xv[r] = *(const float4*)&Xs[(ty * 8 + r) * 32 + kk];

#pragma unroll
            for (int j = 0; j < 4; j++) {
                const ulonglong2 wvA =
                    *(const ulonglong2*)&Ws[(k0 + kk + j) * D_OUT + 8 * tx];
                const ulonglong2 wvB =
                    *(const ulonglong2*)&Ws[(k0 + kk + j) * D_OUT + 8 * tx + 4];
#pragma unroll
                for (int r = 0; r < 8; r++) {
                    const float xs = (j == 0) ? xv[r].x : (j == 1) ? xv[r].y
                                   : (j == 2) ? xv[r].z : xv[r].w;
                    unsigned long long d;
                    asm("mov.b64 %0, {%1, %1};" : "=l"(d) : "f"(xs));
                    asm("fma.rn.f32x2 %0, %1, %2, %0;" : "+l"(acc[r][0]) : "l"(d), "l"(wvA.x));
                    asm("fma.rn.f32x2 %0, %1, %2, %0;" : "+l"(acc[r][1]) : "l"(d), "l"(wvA.y));
                    asm("fma.rn.f32x2 %0, %1, %2, %0;" : "+l"(acc[r][2]) : "l"(d), "l"(wvB.x));
                    asm("fma.rn.f32x2 %0, %1, %2, %0;" : "+l"(acc[r][3]) : "l"(d), "l"(wvB.y));
                }
            }
        }
    }

    // Store 8 rows x 8 cols (guarded: last block covers rows beyond N)
#pragma unroll
    for (int r = 0; r < 8; r++) {
        const int row = row0 + ty * 8 + r;
        if (row < N_NODES) {
            float4 lo, hi;
            asm("mov.b64 {%0, %1}, %2;" : "=f"(lo.x), "=f"(lo.y) : "l"(acc[r][0]));
            asm("mov.b64 {%0, %1}, %2;" : "=f"(lo.z), "=f"(lo.w) : "l"(acc[r][1]));
            asm("mov.b64 {%0, %1}, %2;" : "=f"(hi.x), "=f"(hi.y) : "l"(acc[r][2]));
            asm("mov.b64 {%0, %1}, %2;" : "=f"(hi.z), "=f"(hi.w) : "l"(acc[r][3]));
            float4* p = (float4*)&g_h[(size_t)row * D_OUT + 8 * tx];
            p[0] = lo;
            p[1] = hi;
        }
    }
}

// ---------------------------------------------------------------------------
// Kernel 2: scatter.  out[src] += w * h[dst].  16 lanes per edge (one float4
// each), 8 edges per thread: all index loads batched first, then 8
// independent gather->red chains in flight.
// ---------------------------------------------------------------------------
__global__ void __launch_bounds__(256) scatter_kernel(
    const float* __restrict__ ew,
    const void* __restrict__ srcp,
    const void* __restrict__ dstp,
    float* __restrict__ out) {

    const int t  = blockIdx.x * 256 + threadIdx.x;   // 3.2M threads, exact
    const int c  = t & 15;                           // float4 slot in row
    const int g  = t >> 4;                           // edge octet
    const int e0 = 8 * g;

    const int idx64 = g_idx64;

    const int* sp = (const int*)srcp;
    const int* dp = (const int*)dstp;

    int s[8], d[8];
    float w[8];
#pragma unroll
    for (int i = 0; i < 8; i++) {
        const int e = e0 + i;
        if (idx64) {                 // little-endian low words of int64
            s[i] = __ldg(sp + 2 * e);
            d[i] = __ldg(dp + 2 * e);
        } else {
            s[i] = __ldg(sp + e);
            d[i] = __ldg(dp + e);
        }
        w[i] = __ldg(ew + e);
    }

    float4 v[8];
#pragma unroll
    for (int i = 0; i < 8; i++)
        v[i] = __ldg((const float4*)(g_h + (size_t)d[i] * D_OUT) + c);

#pragma unroll
    for (int i = 0; i < 8; i++) {
        if ((unsigned)s[i] < N_NODES) {
            float* p = out + (size_t)s[i] * D_OUT + 4 * c;
            asm volatile("red.global.add.v4.f32 [%0], {%1, %2, %3, %4};"
                         :: "l"(p), "f"(v[i].x * w[i]), "f"(v[i].y * w[i]),
                            "f"(v[i].z * w[i]), "f"(v[i].w * w[i]) : "memory");
        }
    }
}

// ---------------------------------------------------------------------------
// Kernel 3: in-place ReLU, 2 float4 per thread
// ---------------------------------------------------------------------------
#define RELU_HALF (N_NODES * D_OUT / 4 / 2)   // 800000 float4 per half

__global__ void __launch_bounds__(256) relu_kernel(float4* __restrict__ out) {
    const int i = blockIdx.x * 256 + threadIdx.x;
    float4 a = out[i];
    float4 b = out[i + RELU_HALF];
    a.x = fmaxf(a.x, 0.f); a.y = fmaxf(a.y, 0.f);
    a.z = fmaxf(a.z, 0.f); a.w = fmaxf(a.w, 0.f);
    b.x = fmaxf(b.x, 0.f); b.y = fmaxf(b.y, 0.f);
    b.z = fmaxf(b.z, 0.f); b.w = fmaxf(b.w, 0.f);
    out[i] = a;
    out[i + RELU_HALF] = b;
}

// ---------------------------------------------------------------------------
extern "C" void kernel_launch(void* const* d_in, const int* in_sizes, int n_in,
                              void* d_out, int out_size) {
    const float* x   = (const float*)d_in[0];      // [100000, 128]
    const float* ew  = (const float*)d_in[1];      // [1600000]
    const float* W   = (const float*)d_in[2];      // [128, 64]
    const void*  src = d_in[3];                    // [1600000] int64/int32
    const void*  dst = d_in[4];                    // [1600000] int64/int32
    float* out = (float*)d_out;                    // [100000, 64]

    // zero the poisoned output (graph-capturable, no alloc)
    cudaMemsetAsync(out, 0, (size_t)N_NODES * D_OUT * sizeof(float));

    // h = x @ W (+probe): ceil(100000/128) = 782 blocks
    gemm_kernel<<<(N_NODES + 127) / 128, 128>>>(x, W, src);

    // scatter: E/8 groups * 16 lanes = 3.2M threads -> 12500 blocks
    scatter_kernel<<<(N_EDGES * 2) / 256, 256>>>(ew, src, dst, out);

    // ReLU: 800000 threads -> 3125 blocks
    relu_kernel<<<RELU_HALF / 256, 256>>>((float4*)out);
}